// round 9
// baseline (speedup 1.0000x reference)
#include <cuda_runtime.h>
#include <cuda_fp16.h>
#include <cstdint>
#include <cstddef>

#define Bn 16
#define Tn 2048
#define Dn 1024
#define Hn 512
#define Mn (Bn*Tn)      // 32768
#define Nn 3072
#define Kn 1024

#define MCHUNKS 4
#define MCH (Mn / MCHUNKS)      // 8192 rows = 4 batches
#define BCH (Bn / MCHUNKS)      // 4 batches per chunk

// scratch (static __device__ arrays: allocation-free)
__device__ __half g_Wt[(size_t)Nn * Kn];  // [n'][k], n' = plane*1024 + z*512 + h  (fp16)
__device__ __half g_xh[(size_t)Mn * Kn];  // x in fp16
__device__ __half g_Uh[(size_t)Mn * Nn];  // U in fp16: [m][n'], m = b*T + t

// ------------------------------- helpers -------------------------------
__device__ __forceinline__ uint32_t smem_u32(const void* p) {
    uint32_t a;
    asm("{ .reg .u64 t; cvta.to.shared.u64 t, %1; cvt.u32.u64 %0, t; }" : "=r"(a) : "l"(p));
    return a;
}

#define SWZ(o) ((o) ^ (((o) >> 3) & 0x70))

__device__ __forceinline__ void cp_async16(uint32_t saddr, const void* gptr) {
    asm volatile("cp.async.cg.shared.global [%0], [%1], 16;" :: "r"(saddr), "l"(gptr) : "memory");
}
__device__ __forceinline__ void cp_commit() {
    asm volatile("cp.async.commit_group;" ::: "memory");
}
template<int N> __device__ __forceinline__ void cp_wait() {
    asm volatile("cp.async.wait_group %0;" :: "n"(N) : "memory");
}

#define LDSM4(r, addr) \
    asm volatile("ldmatrix.sync.aligned.m8n8.x4.shared.b16 {%0,%1,%2,%3}, [%4];" \
        : "=r"((r)[0]), "=r"((r)[1]), "=r"((r)[2]), "=r"((r)[3]) : "r"(addr))

#define MMA_F16(d, a, b) \
    asm volatile("mma.sync.aligned.m16n8k16.row.col.f32.f16.f16.f32 " \
        "{%0,%1,%2,%3}, {%4,%5,%6,%7}, {%8,%9}, {%0,%1,%2,%3};" \
        : "+f"((d)[0]), "+f"((d)[1]), "+f"((d)[2]), "+f"((d)[3]) \
        : "r"((a)[0]), "r"((a)[1]), "r"((a)[2]), "r"((a)[3]), "r"((b)[0]), "r"((b)[1]))

// ------------------------- Kernel 0a: x -> fp16 -------------------------
__global__ void __launch_bounds__(256) sru_xh(const float* __restrict__ x) {
    size_t i = (size_t)blockIdx.x * 256 + threadIdx.x;
    float4 v = ((const float4*)x)[i];
    __half2* o = (__half2*)g_xh + i * 2;
    o[0] = __floats2half2_rn(v.x, v.y);
    o[1] = __floats2half2_rn(v.z, v.w);
}

// ------------------------- Kernel 0b: W repack (tiled transpose, fp16) -------------------------
__global__ void __launch_bounds__(256) sru_wt(const float* __restrict__ W) {
    __shared__ float tile[32][33];
    const int tx = threadIdx.x, ty = threadIdx.y;   // 32 x 8
    const int zh0 = blockIdx.x * 32;
    const int d0  = blockIdx.y * 32;
    const int kk  = blockIdx.z;
    #pragma unroll
    for (int r = 0; r < 4; r++) {
        int d = d0 + ty + r * 8;
        int zh = zh0 + tx;
        tile[ty + r * 8][tx] = W[(size_t)d * 3072 + zh * 3 + kk];
    }
    __syncthreads();
    #pragma unroll
    for (int r = 0; r < 4; r++) {
        int zh = zh0 + ty + r * 8;
        int d  = d0 + tx;
        g_Wt[(size_t)(kk * 1024 + zh) * 1024 + d] = __float2half_rn(tile[tx][ty + r * 8]);
    }
}

// ------------------------- Kernel 1: fp16 mma.sync GEMM, 128x128 tiles, 2 CTAs/SM -------------------------
#define BM 128
#define BN 128
#define BK 64
#define NCHUNK (Kn / BK)            // 16
#define ASZ (BM * 128)              // 16384 bytes
#define BSZ (BN * 128)              // 16384 bytes
#define STGB (ASZ + BSZ)            // 32768
#define STAGES 3
#define SMEM_TOTAL (STAGES * STGB)  // 98304

__global__ void __launch_bounds__(256, 2) sru_gemm(int mbase) {
    extern __shared__ __align__(1024) char smem[];
    const uint32_t sb = smem_u32(smem);
    const int tid = threadIdx.x;
    const int lane = tid & 31;
    const int w = tid >> 5;                 // 0..7
    const int m0 = mbase + blockIdx.y * BM;
    const int n0 = blockIdx.x * BN;
    const int wm = (w & 3) * 32;            // 4 m-warps
    const int wn = (w >> 2) * 64;           // 2 n-warps

    const int rr  = tid >> 3;   // 0..31
    const int seg = tid & 7;    // 0..7
    const __half* aS = g_xh + (size_t)(m0 + rr) * Kn + seg * 8;
    const __half* bS = g_Wt + (size_t)(n0 + rr) * Kn + seg * 8;
    uint32_t aO[4], bO[4];
    #pragma unroll
    for (int j = 0; j < 4; j++) {
        uint32_t o = (uint32_t)(rr + 32 * j) * 128 + seg * 16;
        aO[j] = SWZ(o);
        bO[j] = ASZ + SWZ(o);
    }

    auto ldchunk = [&](int c, int s) {
        uint32_t st = sb + (uint32_t)s * STGB;
        const __half* ap = aS + c * BK;
        const __half* bp = bS + c * BK;
        #pragma unroll
        for (int j = 0; j < 4; j++) cp_async16(st + aO[j], ap + (size_t)(32 * j) * Kn);
        #pragma unroll
        for (int j = 0; j < 4; j++) cp_async16(st + bO[j], bp + (size_t)(32 * j) * Kn);
        cp_commit();
    };

    uint32_t aRow[2], aXor[2];
    #pragma unroll
    for (int mi = 0; mi < 2; mi++) {
        uint32_t r = wm + mi * 16 + ((lane & 8) ? 8 : 0) + (lane & 7);
        aRow[mi] = r * 128; aXor[mi] = (r & 7) << 4;
    }
    const uint32_t aHi = (lane & 16) ? 16 : 0;
    uint32_t bRow[4], bXor[4];
    #pragma unroll
    for (int p = 0; p < 4; p++) {
        uint32_t r = wn + p * 16 + ((lane & 16) ? 8 : 0) + (lane & 7);
        bRow[p] = ASZ + r * 128; bXor[p] = (r & 7) << 4;
    }
    const uint32_t bHi = (lane & 8) ? 16 : 0;

    float acc[2][8][4];
    #pragma unroll
    for (int mi = 0; mi < 2; mi++)
        #pragma unroll
        for (int nj = 0; nj < 8; nj++)
            #pragma unroll
            for (int q = 0; q < 4; q++) acc[mi][nj][q] = 0.f;

    ldchunk(0, 0);
    ldchunk(1, 1);

    for (int i = 0; i < NCHUNK; i++) {
        int s = i % 3;
        if (i + 2 < NCHUNK) ldchunk(i + 2, (i + 2) % 3);
        if (i < NCHUNK - 2)       cp_wait<2>();
        else if (i == NCHUNK - 2) cp_wait<1>();
        else                      cp_wait<0>();
        __syncthreads();

        uint32_t st = sb + (uint32_t)s * STGB;
        #pragma unroll
        for (int ks = 0; ks < 4; ks++) {
            uint32_t koff = ks * 32;
            uint32_t ar[2][4], br[4][4];
            #pragma unroll
            for (int mi = 0; mi < 2; mi++)
                LDSM4(ar[mi], st + aRow[mi] + ((koff + aHi) ^ aXor[mi]));
            #pragma unroll
            for (int p = 0; p < 4; p++)
                LDSM4(br[p], st + bRow[p] + ((koff + bHi) ^ bXor[p]));
            #pragma unroll
            for (int mi = 0; mi < 2; mi++)
                #pragma unroll
                for (int nj = 0; nj < 8; nj++)
                    MMA_F16(acc[mi][nj], ar[mi], &br[nj >> 1][(nj & 1) * 2]);
        }
        __syncthreads();
    }

    // fp16 epilogue
    const int rowb = m0 + wm + (lane >> 2);
    const int colb = n0 + wn + (lane & 3) * 2;
    #pragma unroll
    for (int mi = 0; mi < 2; mi++)
        #pragma unroll
        for (int nj = 0; nj < 8; nj++) {
            size_t base = (size_t)(rowb + mi * 16) * Nn + colb + nj * 8;
            *(__half2*)(g_Uh + base) = __floats2half2_rn(acc[mi][nj][0], acc[mi][nj][1]);
            *(__half2*)(g_Uh + base + 8 * (size_t)Nn) = __floats2half2_rn(acc[mi][nj][2], acc[mi][nj][3]);
        }
}

// ------------------------- Kernel 2: SRU scan, 64 steps/tile (2 per lane), 2 ch/warp -------------------------
#define NT64 (Tn / 64)    // 32 tiles

__global__ void __launch_bounds__(512, 2) sru_scan(const float* __restrict__ x,
                                                   const float* __restrict__ bias,
                                                   float* __restrict__ out,
                                                   int bbase) {
    __shared__ __half sbuf[3][64][34];  // g,f,r tiles [t][ch]
    __shared__ float  xbuf[64][33];
    __shared__ float  obuf[64][33];

    const int tid = threadIdx.x;
    const int lane = tid & 31;
    const int w = tid >> 5;             // 0..15
    const int bx = blockIdx.x;          // 128 blocks: hg(16) z(2) b(4)
    const int hg = bx & 15;
    const int z  = (bx >> 4) & 1;
    const int b  = bbase + (bx >> 5);
    const int h0 = hg * 32;
    const int fwd = (z == 0);
    const int c0 = 2 * w, c1 = 2 * w + 1;

    const float bf0 = bias[z * 1024 + h0 + c0];
    const float bf1 = bias[z * 1024 + h0 + c1];
    const float br0 = bias[z * 1024 + 512 + h0 + c0];
    const float br1 = bias[z * 1024 + 512 + h0 + c1];

    const size_t bT = (size_t)b * Tn;

    uint4 ru[2], rx[4];
    auto load_tile = [&](int it) {
        long t0 = fwd ? (long)it * 64 : (long)(NT64 - 1 - it) * 64;
        if (tid < 384) {
            #pragma unroll
            for (int j = 0; j < 2; j++) {
                int q = tid + 384 * j;
                int p = q >> 8, rem = q & 255;
                int t = rem >> 2, sg = rem & 3;
                ru[j] = *(const uint4*)(g_Uh + (bT + t0 + t) * Nn + (size_t)p * 1024 + z * 512 + h0 + sg * 8);
            }
        } else {
            #pragma unroll
            for (int j = 0; j < 4; j++) {
                int idx = (tid - 384) + 128 * j;
                int t = idx >> 3, sg = idx & 7;
                rx[j] = *(const uint4*)(x + (bT + t0 + t) * Dn + z * 512 + h0 + sg * 4);
            }
        }
    };

    load_tile(0);
    float carry0 = 0.f, carry1 = 0.f;
    const int pos0 = 2 * lane, pos1 = 2 * lane + 1;
    const int row0 = fwd ? pos0 : 63 - pos0;
    const int row1 = fwd ? pos1 : 63 - pos1;

    for (int it = 0; it < NT64; it++) {
        if (tid < 384) {
            #pragma unroll
            for (int j = 0; j < 2; j++) {
                int q = tid + 384 * j;
                int p = q >> 8, rem = q & 255;
                int t = rem >> 2, sg = rem & 3;
                uint32_t* dst = (uint32_t*)&sbuf[p][t][sg * 8];
                dst[0] = ru[j].x; dst[1] = ru[j].y; dst[2] = ru[j].z; dst[3] = ru[j].w;
            }
        } else {
            #pragma unroll
            for (int j = 0; j < 4; j++) {
                int idx = (tid - 384) + 128 * j;
                int t = idx >> 3, sg = idx & 7;
                float* d = &xbuf[t][sg * 4];
                d[0] = __uint_as_float(rx[j].x); d[1] = __uint_as_float(rx[j].y);
                d[2] = __uint_as_float(rx[j].z); d[3] = __uint_as_float(rx[j].w);
            }
        }
        __syncthreads();
        if (it + 1 < NT64) load_tile(it + 1);   // prefetch overlaps compute

        float2 Ga = __half22float2(*(const __half2*)&sbuf[0][row0][c0]);
        float2 Fa = __half22float2(*(const __half2*)&sbuf[1][row0][c0]);
        float2 Ra = __half22float2(*(const __half2*)&sbuf[2][row0][c0]);
        float2 Gb = __half22float2(*(const __half2*)&sbuf[0][row1][c0]);
        float2 Fb = __half22float2(*(const __half2*)&sbuf[1][row1][c0]);
        float2 Rb = __half22float2(*(const __half2*)&sbuf[2][row1][c0]);
        float xa0 = xbuf[row0][c0], xa1 = xbuf[row0][c1];
        float xb0 = xbuf[row1][c0], xb1 = xbuf[row1][c1];

        float a00 = __fdividef(1.f, 1.f + __expf(-(Fa.x + bf0)));
        float a01 = __fdividef(1.f, 1.f + __expf(-(Fb.x + bf0)));
        float a10 = __fdividef(1.f, 1.f + __expf(-(Fa.y + bf1)));
        float a11 = __fdividef(1.f, 1.f + __expf(-(Fb.y + bf1)));
        float b00 = (1.f - a00) * Ga.x;
        float b01 = (1.f - a01) * Gb.x;
        float b10 = (1.f - a10) * Ga.y;
        float b11 = (1.f - a11) * Gb.y;

        float A0 = a01 * a00, B0 = fmaf(a01, b00, b01);
        float A1 = a11 * a10, B1 = fmaf(a11, b10, b11);

        #pragma unroll
        for (int d = 1; d < 32; d <<= 1) {
            float Ap0 = __shfl_up_sync(0xFFFFFFFFu, A0, d);
            float Bp0 = __shfl_up_sync(0xFFFFFFFFu, B0, d);
            float Ap1 = __shfl_up_sync(0xFFFFFFFFu, A1, d);
            float Bp1 = __shfl_up_sync(0xFFFFFFFFu, B1, d);
            if (lane >= d) {
                B0 = fmaf(A0, Bp0, B0); A0 *= Ap0;
                B1 = fmaf(A1, Bp1, B1); A1 *= Ap1;
            }
        }
        float Ae0 = __shfl_up_sync(0xFFFFFFFFu, A0, 1);
        float Be0 = __shfl_up_sync(0xFFFFFFFFu, B0, 1);
        float Ae1 = __shfl_up_sync(0xFFFFFFFFu, A1, 1);
        float Be1 = __shfl_up_sync(0xFFFFFFFFu, B1, 1);
        if (lane == 0) { Ae0 = 1.f; Be0 = 0.f; Ae1 = 1.f; Be1 = 0.f; }
        float cin0 = fmaf(Ae0, carry0, Be0);
        float cin1 = fmaf(Ae1, carry1, Be1);
        float ca0 = fmaf(a00, cin0, b00);
        float cb0 = fmaf(a01, ca0,  b01);
        float ca1 = fmaf(a10, cin1, b10);
        float cb1 = fmaf(a11, ca1,  b11);
        float At0 = __shfl_sync(0xFFFFFFFFu, A0, 31);
        float Bt0 = __shfl_sync(0xFFFFFFFFu, B0, 31);
        float At1 = __shfl_sync(0xFFFFFFFFu, A1, 31);
        float Bt1 = __shfl_sync(0xFFFFFFFFu, B1, 31);
        carry0 = fmaf(At0, carry0, Bt0);
        carry1 = fmaf(At1, carry1, Bt1);

        float rva0 = __fdividef(1.f, 1.f + __expf(-(Ra.x + br0)));
        float rvb0 = __fdividef(1.f, 1.f + __expf(-(Rb.x + br0)));
        float rva1 = __fdividef(1.f, 1.f + __expf(-(Ra.y + br1)));
        float rvb1 = __fdividef(1.f, 1.f + __expf(-(Rb.y + br1)));
        float tha0 = 1.f - 2.f * __fdividef(1.f, 1.f + __expf(2.f * ca0));
        float thb0 = 1.f - 2.f * __fdividef(1.f, 1.f + __expf(2.f * cb0));
        float tha1 = 1.f - 2.f * __fdividef(1.f, 1.f + __expf(2.f * ca1));
        float thb1 = 1.f - 2.f * __fdividef(1.f, 1.f + __expf(2.f * cb1));
        obuf[row0][c0] = fmaf(rva0, tha0 - xa0, xa0);
        obuf[row1][c0] = fmaf(rvb0, thb0 - xb0, xb0);
        obuf[row0][c1] = fmaf(rva1, tha1 - xa1, xa1);
        obuf[row1][c1] = fmaf(rvb1, thb1 - xb1, xb1);
        __syncthreads();

        {
            long t0 = fwd ? (long)it * 64 : (long)(NT64 - 1 - it) * 64;
            int t = tid >> 3, sg = tid & 7;
            float4 v = make_float4(obuf[t][sg * 4], obuf[t][sg * 4 + 1],
                                   obuf[t][sg * 4 + 2], obuf[t][sg * 4 + 3]);
            *(float4*)(out + (bT + t0 + t) * Dn + z * 512 + h0 + sg * 4) = v;
        }
    }

    if (lane == 0) {
        out[(size_t)Bn * Tn * Dn + (size_t)b * 1024 + z * 512 + h0 + c0] = carry0;
        out[(size_t)Bn * Tn * Dn + (size_t)b * 1024 + z * 512 + h0 + c1] = carry1;
    }
}

// ------------------------------- launch -------------------------------
extern "C" void kernel_launch(void* const* d_in, const int* in_sizes, int n_in,
                              void* d_out, int out_size) {
    const float* x    = (const float*)d_in[0];
    const float* W    = (const float*)d_in[1];
    const float* bias = (const float*)d_in[2];
    float* out = (float*)d_out;
    (void)in_sizes; (void)n_in; (void)out_size;

    cudaFuncSetAttribute(sru_gemm, cudaFuncAttributeMaxDynamicSharedMemorySize, SMEM_TOTAL);

    cudaStream_t s0 = 0;
    cudaStream_t sA;
    cudaStreamCreateWithFlags(&sA, cudaStreamNonBlocking);
    cudaEvent_t evFork, evW, evG[MCHUNKS], evJoin;
    cudaEventCreateWithFlags(&evFork, cudaEventDisableTiming);
    cudaEventCreateWithFlags(&evW,    cudaEventDisableTiming);
    cudaEventCreateWithFlags(&evJoin, cudaEventDisableTiming);
    for (int k = 0; k < MCHUNKS; k++)
        cudaEventCreateWithFlags(&evG[k], cudaEventDisableTiming);

    // fork side stream; W repack runs there, overlapped with x->fp16
    cudaEventRecord(evFork, s0);
    cudaStreamWaitEvent(sA, evFork, 0);
    sru_wt<<<dim3(32, 32, 3), dim3(32, 8), 0, sA>>>(W);
    cudaEventRecord(evW, sA);

    sru_xh<<<(Mn * (Kn / 4)) / 256, 256, 0, s0>>>(x);
    cudaStreamWaitEvent(s0, evW, 0);    // GEMM needs g_Wt

    // pipelined GEMM chunks (s0) with overlapped scan chunks (sA)
    for (int k = 0; k < MCHUNKS; k++) {
        sru_gemm<<<dim3(Nn / BN, MCH / BM), 256, SMEM_TOTAL, s0>>>(k * MCH);
        cudaEventRecord(evG[k], s0);
        cudaStreamWaitEvent(sA, evG[k], 0);
        sru_scan<<<128, 512, 0, sA>>>(x, bias, out, k * BCH);
    }
    cudaEventRecord(evJoin, sA);
    cudaStreamWaitEvent(s0, evJoin, 0);

    cudaEventDestroy(evFork);
    cudaEventDestroy(evW);
    cudaEventDestroy(evJoin);
    for (int k = 0; k < MCHUNKS; k++) cudaEventDestroy(evG[k]);
    cudaStreamDestroy(sA);
}

// round 10
// speedup vs baseline: 1.0776x; 1.0776x over previous
#include <cuda_runtime.h>
#include <cuda_fp16.h>
#include <cstdint>
#include <cstddef>

#define Bn 16
#define Tn 2048
#define Dn 1024
#define Hn 512
#define Mn (Bn*Tn)      // 32768
#define Nn 3072
#define Kn 1024

// scratch (static __device__ arrays: allocation-free)
__device__ __half g_Wt[(size_t)Nn * Kn];  // [n'][k], n' = plane*1024 + z*512 + h  (fp16)
__device__ __half g_xh[(size_t)Mn * Kn];  // x in fp16
__device__ __half g_Uh[(size_t)Mn * Nn];  // U in fp16: [m][n'], m = b*T + t

// ------------------------------- helpers -------------------------------
__device__ __forceinline__ uint32_t smem_u32(const void* p) {
    uint32_t a;
    asm("{ .reg .u64 t; cvta.to.shared.u64 t, %1; cvt.u32.u64 %0, t; }" : "=r"(a) : "l"(p));
    return a;
}

#define SWZ(o) ((o) ^ (((o) >> 3) & 0x70))

__device__ __forceinline__ void cp_async16(uint32_t saddr, const void* gptr) {
    asm volatile("cp.async.cg.shared.global [%0], [%1], 16;" :: "r"(saddr), "l"(gptr) : "memory");
}
__device__ __forceinline__ void cp_commit() {
    asm volatile("cp.async.commit_group;" ::: "memory");
}
template<int N> __device__ __forceinline__ void cp_wait() {
    asm volatile("cp.async.wait_group %0;" :: "n"(N) : "memory");
}

#define LDSM4(r, addr) \
    asm volatile("ldmatrix.sync.aligned.m8n8.x4.shared.b16 {%0,%1,%2,%3}, [%4];" \
        : "=r"((r)[0]), "=r"((r)[1]), "=r"((r)[2]), "=r"((r)[3]) : "r"(addr))

#define MMA_F16(d, a, b) \
    asm volatile("mma.sync.aligned.m16n8k16.row.col.f32.f16.f16.f32 " \
        "{%0,%1,%2,%3}, {%4,%5,%6,%7}, {%8,%9}, {%0,%1,%2,%3};" \
        : "+f"((d)[0]), "+f"((d)[1]), "+f"((d)[2]), "+f"((d)[3]) \
        : "r"((a)[0]), "r"((a)[1]), "r"((a)[2]), "r"((a)[3]), "r"((b)[0]), "r"((b)[1]))

// ------------------------- Kernel 0a: x -> fp16 -------------------------
__global__ void __launch_bounds__(256) sru_xh(const float* __restrict__ x) {
    size_t i = (size_t)blockIdx.x * 256 + threadIdx.x;
    float4 v = ((const float4*)x)[i];
    __half2* o = (__half2*)g_xh + i * 2;
    o[0] = __floats2half2_rn(v.x, v.y);
    o[1] = __floats2half2_rn(v.z, v.w);
}

// ------------------------- Kernel 0b: W repack (tiled transpose, fp16) -------------------------
__global__ void __launch_bounds__(256) sru_wt(const float* __restrict__ W) {
    __shared__ float tile[32][33];
    const int tx = threadIdx.x, ty = threadIdx.y;   // 32 x 8
    const int zh0 = blockIdx.x * 32;
    const int d0  = blockIdx.y * 32;
    const int kk  = blockIdx.z;
    #pragma unroll
    for (int r = 0; r < 4; r++) {
        int d = d0 + ty + r * 8;
        int zh = zh0 + tx;
        tile[ty + r * 8][tx] = W[(size_t)d * 3072 + zh * 3 + kk];
    }
    __syncthreads();
    #pragma unroll
    for (int r = 0; r < 4; r++) {
        int zh = zh0 + ty + r * 8;
        int d  = d0 + tx;
        g_Wt[(size_t)(kk * 1024 + zh) * 1024 + d] = __float2half_rn(tile[tx][ty + r * 8]);
    }
}

// ------------------------- Kernel 1: fp16 mma.sync GEMM, 128x128 tiles, 2 CTAs/SM -------------------------
#define BM 128
#define BN 128
#define BK 64
#define NCHUNK (Kn / BK)            // 16
#define ASZ (BM * 128)              // 16384 bytes
#define BSZ (BN * 128)              // 16384 bytes
#define STGB (ASZ + BSZ)            // 32768
#define STAGES 3
#define SMEM_TOTAL (STAGES * STGB)  // 98304

__global__ void __launch_bounds__(256, 2) sru_gemm() {
    extern __shared__ __align__(1024) char smem[];
    const uint32_t sb = smem_u32(smem);
    const int tid = threadIdx.x;
    const int lane = tid & 31;
    const int w = tid >> 5;                 // 0..7
    const int m0 = blockIdx.y * BM;
    const int n0 = blockIdx.x * BN;
    const int wm = (w & 3) * 32;            // 4 m-warps
    const int wn = (w >> 2) * 64;           // 2 n-warps

    const int rr  = tid >> 3;   // 0..31
    const int seg = tid & 7;    // 0..7
    const __half* aS = g_xh + (size_t)(m0 + rr) * Kn + seg * 8;
    const __half* bS = g_Wt + (size_t)(n0 + rr) * Kn + seg * 8;
    uint32_t aO[4], bO[4];
    #pragma unroll
    for (int j = 0; j < 4; j++) {
        uint32_t o = (uint32_t)(rr + 32 * j) * 128 + seg * 16;
        aO[j] = SWZ(o);
        bO[j] = ASZ + SWZ(o);
    }

    auto ldchunk = [&](int c, int s) {
        uint32_t st = sb + (uint32_t)s * STGB;
        const __half* ap = aS + c * BK;
        const __half* bp = bS + c * BK;
        #pragma unroll
        for (int j = 0; j < 4; j++) cp_async16(st + aO[j], ap + (size_t)(32 * j) * Kn);
        #pragma unroll
        for (int j = 0; j < 4; j++) cp_async16(st + bO[j], bp + (size_t)(32 * j) * Kn);
        cp_commit();
    };

    uint32_t aRow[2], aXor[2];
    #pragma unroll
    for (int mi = 0; mi < 2; mi++) {
        uint32_t r = wm + mi * 16 + ((lane & 8) ? 8 : 0) + (lane & 7);
        aRow[mi] = r * 128; aXor[mi] = (r & 7) << 4;
    }
    const uint32_t aHi = (lane & 16) ? 16 : 0;
    uint32_t bRow[4], bXor[4];
    #pragma unroll
    for (int p = 0; p < 4; p++) {
        uint32_t r = wn + p * 16 + ((lane & 16) ? 8 : 0) + (lane & 7);
        bRow[p] = ASZ + r * 128; bXor[p] = (r & 7) << 4;
    }
    const uint32_t bHi = (lane & 8) ? 16 : 0;

    float acc[2][8][4];
    #pragma unroll
    for (int mi = 0; mi < 2; mi++)
        #pragma unroll
        for (int nj = 0; nj < 8; nj++)
            #pragma unroll
            for (int q = 0; q < 4; q++) acc[mi][nj][q] = 0.f;

    ldchunk(0, 0);
    ldchunk(1, 1);

    for (int i = 0; i < NCHUNK; i++) {
        int s = i % 3;
        if (i + 2 < NCHUNK) ldchunk(i + 2, (i + 2) % 3);
        if (i < NCHUNK - 2)       cp_wait<2>();
        else if (i == NCHUNK - 2) cp_wait<1>();
        else                      cp_wait<0>();
        __syncthreads();

        uint32_t st = sb + (uint32_t)s * STGB;
        #pragma unroll
        for (int ks = 0; ks < 4; ks++) {
            uint32_t koff = ks * 32;
            uint32_t ar[2][4], br[4][4];
            #pragma unroll
            for (int mi = 0; mi < 2; mi++)
                LDSM4(ar[mi], st + aRow[mi] + ((koff + aHi) ^ aXor[mi]));
            #pragma unroll
            for (int p = 0; p < 4; p++)
                LDSM4(br[p], st + bRow[p] + ((koff + bHi) ^ bXor[p]));
            #pragma unroll
            for (int mi = 0; mi < 2; mi++)
                #pragma unroll
                for (int nj = 0; nj < 8; nj++)
                    MMA_F16(acc[mi][nj], ar[mi], &br[nj >> 1][(nj & 1) * 2]);
        }
        __syncthreads();
    }

    // fp16 epilogue
    const int rowb = m0 + wm + (lane >> 2);
    const int colb = n0 + wn + (lane & 3) * 2;
    #pragma unroll
    for (int mi = 0; mi < 2; mi++)
        #pragma unroll
        for (int nj = 0; nj < 8; nj++) {
            size_t base = (size_t)(rowb + mi * 16) * Nn + colb + nj * 8;
            *(__half2*)(g_Uh + base) = __floats2half2_rn(acc[mi][nj][0], acc[mi][nj][1]);
            *(__half2*)(g_Uh + base + 8 * (size_t)Nn) = __floats2half2_rn(acc[mi][nj][2], acc[mi][nj][3]);
        }
}

// ------------------------- Kernel 2: SRU scan, 64 steps/tile, 4 ch/warp (ILP-4) -------------------------
// Block: 512 threads = 16 warps; one (b,z) and 64 h-channels; warp w owns channels 4w..4w+3.
// Lane l covers timesteps 2l, 2l+1: local affine compose, pair K-S scan over 4 chains, fix-up.
#define NT64 (Tn / 64)    // 32 tiles

__global__ void __launch_bounds__(512, 2) sru_scan(const float* __restrict__ bias,
                                                   float* __restrict__ out) {
    __shared__ __half sbuf[3][64][66];  // g,f,r tiles [t][ch], 33-word rows (odd -> bank-clean)
    __shared__ __half xbuf[64][66];
    __shared__ float  obuf[64][65];

    const int tid = threadIdx.x;
    const int lane = tid & 31;
    const int w = tid >> 5;             // 0..15
    const int bx = blockIdx.x;          // 256 blocks: hg(8) z(2) b(16)
    const int hg = bx & 7;
    const int z  = (bx >> 3) & 1;
    const int b  = bx >> 4;
    const int h0 = hg * 64;
    const int fwd = (z == 0);
    const int c0 = 4 * w;

    float bf[4], br[4];
    #pragma unroll
    for (int c = 0; c < 4; c++) {
        bf[c] = bias[z * 1024 + h0 + c0 + c];
        br[c] = bias[z * 1024 + 512 + h0 + c0 + c];
    }

    const size_t bT = (size_t)b * Tn;
    const int tL = tid >> 3, sgL = tid & 7;     // loader role: row tL, 8-half seg sgL

    uint4 ru[3], rx;
    auto load_tile = [&](int it) {
        long t0 = fwd ? (long)it * 64 : (long)(NT64 - 1 - it) * 64;
        #pragma unroll
        for (int p = 0; p < 3; p++)
            ru[p] = *(const uint4*)(g_Uh + (bT + t0 + tL) * Nn + (size_t)p * 1024 + z * 512 + h0 + sgL * 8);
        rx = *(const uint4*)(g_xh + (bT + t0 + tL) * Kn + z * 512 + h0 + sgL * 8);
    };

    load_tile(0);
    float carry[4] = {0.f, 0.f, 0.f, 0.f};
    const int row0 = fwd ? 2 * lane     : 63 - 2 * lane;
    const int row1 = fwd ? 2 * lane + 1 : 62 - 2 * lane;

    for (int it = 0; it < NT64; it++) {
        // stage regs -> smem (scalar word stores; odd-word row stride)
        #pragma unroll
        for (int p = 0; p < 3; p++) {
            uint32_t* d = (uint32_t*)&sbuf[p][tL][sgL * 8];
            d[0] = ru[p].x; d[1] = ru[p].y; d[2] = ru[p].z; d[3] = ru[p].w;
        }
        {
            uint32_t* d = (uint32_t*)&xbuf[tL][sgL * 8];
            d[0] = rx.x; d[1] = rx.y; d[2] = rx.z; d[3] = rx.w;
        }
        __syncthreads();
        if (it + 1 < NT64) load_tile(it + 1);   // prefetch overlaps compute

        // read 2 timesteps x 4 channels
        float2 Ga01 = __half22float2(*(const __half2*)&sbuf[0][row0][c0]);
        float2 Ga23 = __half22float2(*(const __half2*)&sbuf[0][row0][c0 + 2]);
        float2 Fa01 = __half22float2(*(const __half2*)&sbuf[1][row0][c0]);
        float2 Fa23 = __half22float2(*(const __half2*)&sbuf[1][row0][c0 + 2]);
        float2 Ra01 = __half22float2(*(const __half2*)&sbuf[2][row0][c0]);
        float2 Ra23 = __half22float2(*(const __half2*)&sbuf[2][row0][c0 + 2]);
        float2 Xa01 = __half22float2(*(const __half2*)&xbuf[row0][c0]);
        float2 Xa23 = __half22float2(*(const __half2*)&xbuf[row0][c0 + 2]);
        float2 Gb01 = __half22float2(*(const __half2*)&sbuf[0][row1][c0]);
        float2 Gb23 = __half22float2(*(const __half2*)&sbuf[0][row1][c0 + 2]);
        float2 Fb01 = __half22float2(*(const __half2*)&sbuf[1][row1][c0]);
        float2 Fb23 = __half22float2(*(const __half2*)&sbuf[1][row1][c0 + 2]);
        float2 Rb01 = __half22float2(*(const __half2*)&sbuf[2][row1][c0]);
        float2 Rb23 = __half22float2(*(const __half2*)&sbuf[2][row1][c0 + 2]);
        float2 Xb01 = __half22float2(*(const __half2*)&xbuf[row1][c0]);
        float2 Xb23 = __half22float2(*(const __half2*)&xbuf[row1][c0 + 2]);

        float Ga[4] = {Ga01.x, Ga01.y, Ga23.x, Ga23.y};
        float Fa[4] = {Fa01.x, Fa01.y, Fa23.x, Fa23.y};
        float Ra[4] = {Ra01.x, Ra01.y, Ra23.x, Ra23.y};
        float Xa[4] = {Xa01.x, Xa01.y, Xa23.x, Xa23.y};
        float Gb[4] = {Gb01.x, Gb01.y, Gb23.x, Gb23.y};
        float Fb[4] = {Fb01.x, Fb01.y, Fb23.x, Fb23.y};
        float Rb[4] = {Rb01.x, Rb01.y, Rb23.x, Rb23.y};
        float Xb[4] = {Xb01.x, Xb01.y, Xb23.x, Xb23.y};

        float aa[4], ab[4], ba[4], bb[4], A[4], Bv[4];
        #pragma unroll
        for (int c = 0; c < 4; c++) {
            aa[c] = __fdividef(1.f, 1.f + __expf(-(Fa[c] + bf[c])));   // step0 coeff
            ab[c] = __fdividef(1.f, 1.f + __expf(-(Fb[c] + bf[c])));   // step1 coeff
            ba[c] = (1.f - aa[c]) * Ga[c];
            bb[c] = (1.f - ab[c]) * Gb[c];
            A[c]  = ab[c] * aa[c];                 // pair compose
            Bv[c] = fmaf(ab[c], ba[c], bb[c]);
        }

        // Kogge-Stone inclusive scan over pairs, 4 channels interleaved
        #pragma unroll
        for (int d = 1; d < 32; d <<= 1) {
            float Ap[4], Bp[4];
            #pragma unroll
            for (int c = 0; c < 4; c++) {
                Ap[c] = __shfl_up_sync(0xFFFFFFFFu, A[c], d);
                Bp[c] = __shfl_up_sync(0xFFFFFFFFu, Bv[c], d);
            }
            if (lane >= d) {
                #pragma unroll
                for (int c = 0; c < 4; c++) {
                    Bv[c] = fmaf(A[c], Bp[c], Bv[c]);
                    A[c] *= Ap[c];
                }
            }
        }

        float ca[4], cb[4];
        #pragma unroll
        for (int c = 0; c < 4; c++) {
            float Ae = __shfl_up_sync(0xFFFFFFFFu, A[c], 1);
            float Be = __shfl_up_sync(0xFFFFFFFFu, Bv[c], 1);
            if (lane == 0) { Ae = 1.f; Be = 0.f; }
            float cin = fmaf(Ae, carry[c], Be);
            ca[c] = fmaf(aa[c], cin, ba[c]);
            cb[c] = fmaf(ab[c], ca[c], bb[c]);
            float At = __shfl_sync(0xFFFFFFFFu, A[c], 31);
            float Bt = __shfl_sync(0xFFFFFFFFu, Bv[c], 31);
            carry[c] = fmaf(At, carry[c], Bt);
        }

        #pragma unroll
        for (int c = 0; c < 4; c++) {
            float rva = __fdividef(1.f, 1.f + __expf(-(Ra[c] + br[c])));
            float rvb = __fdividef(1.f, 1.f + __expf(-(Rb[c] + br[c])));
            float tha = 1.f - 2.f * __fdividef(1.f, 1.f + __expf(2.f * ca[c]));
            float thb = 1.f - 2.f * __fdividef(1.f, 1.f + __expf(2.f * cb[c]));
            obuf[row0][c0 + c] = fmaf(rva, tha - Xa[c], Xa[c]);
            obuf[row1][c0 + c] = fmaf(rvb, thb - Xb[c], Xb[c]);
        }
        __syncthreads();

        // coalesced store: 1024 float4 over 512 threads (2 each)
        {
            long t0 = fwd ? (long)it * 64 : (long)(NT64 - 1 - it) * 64;
            #pragma unroll
            for (int j = 0; j < 2; j++) {
                int idx = tid + 512 * j;
                int t = idx >> 4, sg = idx & 15;
                float4 v = make_float4(obuf[t][sg * 4], obuf[t][sg * 4 + 1],
                                       obuf[t][sg * 4 + 2], obuf[t][sg * 4 + 3]);
                *(float4*)(out + (bT + t0 + t) * Dn + z * 512 + h0 + sg * 4) = v;
            }
        }
        __syncthreads();
    }

    // c_last: (B, 1, 2H) appended after out
    if (lane == 0) {
        float4 v = make_float4(carry[0], carry[1], carry[2], carry[3]);
        *(float4*)(out + (size_t)Bn * Tn * Dn + (size_t)b * 1024 + z * 512 + h0 + c0) = v;
    }
}

// ------------------------------- launch -------------------------------
extern "C" void kernel_launch(void* const* d_in, const int* in_sizes, int n_in,
                              void* d_out, int out_size) {
    const float* x    = (const float*)d_in[0];
    const float* W    = (const float*)d_in[1];
    const float* bias = (const float*)d_in[2];
    float* out = (float*)d_out;
    (void)in_sizes; (void)n_in; (void)out_size;

    cudaFuncSetAttribute(sru_gemm, cudaFuncAttributeMaxDynamicSharedMemorySize, SMEM_TOTAL);

    sru_xh  <<<(Mn * (Kn / 4)) / 256, 256>>>(x);
    sru_wt  <<<dim3(32, 32, 3), dim3(32, 8)>>>(W);
    sru_gemm<<<dim3(Nn / BN, Mn / BM), 256, SMEM_TOTAL>>>();
    sru_scan<<<256, 512>>>(bias, out);
}